// round 10
// baseline (speedup 1.0000x reference)
#include <cuda_runtime.h>
#include <cuda_bf16.h>
#include <cstdint>

#define BB 16
#define HH 180
#define WW 240
#define NC (BB*HH*WW)      /* 691200 full-res cells            */
#define HV (HH/2)          /* 90                               */
#define WV (WW/2)          /* 120                              */
#define VPB (HV*WV)        /* 10800 voxels per batch           */
#define NV (BB*VPB)        /* 172800 half-res voxels           */
#define NVP (NV/2)         /* 86400 voxel pairs                */

#define TILE_EV 1024
#define TILE_F4 (TILE_EV * 5 / 4)   /* 1280 float4 = 20 KB smem */

// Scratch (__device__ globals — no allocations allowed)
__device__ float2   g_ct[NC];      // per full-res cell: (count, tsum_raw)
// g_small: [0]=barrier0 [1]=barrier1 [2..17]=per-batch tmax bits. One memset/launch.
__device__ unsigned g_small[32];

// ---------------------------------------------------------------------------
__device__ __forceinline__ void grid_barrier(unsigned* bar, unsigned nb) {
    __syncthreads();
    if (threadIdx.x == 0) {
        __threadfence();                       // release all prior writes/reds
        unsigned arrived = atomicAdd(bar, 1) + 1;
        if (arrived < nb) {
            while (atomicAdd(bar, 0u) < nb) __nanosleep(64);
        }
        __threadfence();                       // acquire others' writes
    }
    __syncthreads();
}

// ---------------------------------------------------------------------------
__global__ void __launch_bounds__(256) fused_kernel(
    const float4* __restrict__ evq, int n, int nTiles, float* __restrict__ out)
{
    __shared__ float4 sbuf[TILE_F4];
    const float* sf = reinterpret_cast<const float*>(sbuf);

    const unsigned FULL = 0xffffffffu;
    const unsigned NB   = gridDim.x;
    int lane = threadIdx.x & 31;
    int gtid = blockIdx.x * 256 + threadIdx.x;
    int gnum = NB * 256;

    // ================= phase 0: zero the accumulator =================
    {
        float4* z = reinterpret_cast<float4*>(g_ct);
        for (int j = gtid; j < NC / 2; j += gnum)
            z[j] = make_float4(0.f, 0.f, 0.f, 0.f);
    }
    grid_barrier(&g_small[0], NB);

    // ================= phase 1: scatter =================
    unsigned loc = 0;  // lane l (<16) carries running max-bits for batch l
    long long totF4 = (long long)n * 5 / 4;

    for (int tile = blockIdx.x; tile < nTiles; tile += NB) {
        long long baseF4 = (long long)tile * TILE_F4;
        #pragma unroll
        for (int q = 0; q < 5; ++q) {
            int idx = threadIdx.x + q * 256;
            long long g = baseF4 + idx;
            if (g < totF4) sbuf[idx] = __ldg(evq + g);
        }
        __syncthreads();

        long long baseEv = (long long)tile * TILE_EV;
        #pragma unroll
        for (int q = 0; q < 4; ++q) {
            int le = threadIdx.x + q * 256;
            long long e = baseEv + le;
            bool valid = (e < (long long)n);
            float x = 0.f, y = 0.f, t = 0.f, b = 0.f;
            if (valid) {
                int s = 5 * le;
                x = sf[s + 0];
                y = sf[s + 1];
                t = sf[s + 2];
                b = sf[s + 4];
            }
            int bi = (int)b, xi = (int)x, yi = (int)y;

            if (valid) {
                // single fused atomic per event: (count, raw t) into full-res cell
                int idx_c = xi + WW * yi + (WW * HH) * bi;
                if ((unsigned)idx_c < (unsigned)NC)
                    asm volatile("red.global.add.v2.f32 [%0], {%1, %2};"
                                 :: "l"(&g_ct[idx_c]), "f"(1.0f), "f"(t) : "memory");
            }

            // per-batch time max: b sorted -> warps almost always batch-uniform
            unsigned tb = __float_as_uint(t);
            int b0 = __shfl_sync(FULL, bi, 0);
            if (__all_sync(FULL, bi == b0)) {
                unsigned wm = __reduce_max_sync(FULL, tb);
                if (lane == b0) loc = max(loc, wm);
            } else {
                for (int l = 0; l < 32; ++l) {
                    int      bl = __shfl_sync(FULL, bi, l);
                    unsigned tl = __shfl_sync(FULL, tb, l);
                    if (lane == bl) loc = max(loc, tl);
                }
            }
        }
        __syncthreads();
    }

    // block-level tmax reduction -> global (before the barrier)
    __shared__ unsigned smax[BB];
    if (threadIdx.x < BB) smax[threadIdx.x] = 0u;
    __syncthreads();
    if (lane < BB && loc) atomicMax(&smax[lane], loc);
    __syncthreads();
    if (threadIdx.x < BB && smax[threadIdx.x])
        atomicMax(&g_small[2 + threadIdx.x], smax[threadIdx.x]);

    grid_barrier(&g_small[1], NB);

    // ================= phase 2: finalize =================
    // One thread per PAIR of adjacent half-res voxels (jj = 2u, 2u+1); pairs
    // never straddle the jj<60 / jj>=60 spill boundary. Per the reference's
    // idx_k = floor(x/2) + 60*y + 10800*b quirk, voxel (k,ii,jj) aggregates:
    //   even row y=2ii, cols [2jj,2jj+1]                      (always)
    //   jj>=60: odd row y=2ii+1, cols [2jj-120,2jj-119]       (same batch)
    //   jj<60, ii>=1: odd row y=2ii-1, cols [120+2jj,121+2jj]
    //   jj<60, ii==0, k>=1: batch k-1, row 179, cols [120+2jj,121+2jj]
    {
        float*  cont    = out;
        float*  counter = out + NC;
        float*  timer   = out + NC + NV;
        float*  dxo     = out + NC + 2 * NV;
        float*  dyo     = out + NC + 3 * NV;
        const float4* Cq = reinterpret_cast<const float4*>(g_ct);

        for (int vp = gtid; vp < NVP; vp += gnum) {
            int k  = vp / (VPB / 2);
            int rp = vp - k * (VPB / 2);
            int ii = rp / (WV / 2);
            int u  = rp - ii * (WV / 2);
            int v0 = k * VPB + ii * WV + 2 * u;

            int re = k * (HH * WW) + (2 * ii) * WW + 4 * u;
            int ro = re + WW;

            float4 ea = Cq[(re >> 1) + 0];
            float4 eb = Cq[(re >> 1) + 1];
            float4 oa = Cq[(ro >> 1) + 0];
            float4 ob = Cq[(ro >> 1) + 1];

            reinterpret_cast<float4*>(cont + re)[0] = make_float4(ea.x, ea.z, eb.x, eb.z);
            reinterpret_cast<float4*>(cont + ro)[0] = make_float4(oa.x, oa.z, ob.x, ob.z);

            reinterpret_cast<float2*>(dxo + v0)[0] =
                make_float2((oa.x - oa.z) + (ea.x - ea.z), (ob.x - ob.z) + (eb.x - eb.z));
            reinterpret_cast<float2*>(dyo + v0)[0] =
                make_float2((ea.x - oa.x) + (ea.z - oa.z), (eb.x - ob.x) + (eb.z - ob.z));

            float Tk = __uint_as_float(g_small[2 + k]);
            if (Tk == 0.0f) Tk = 1.0f;

            float cnt0 = ea.x + ea.z, ts0 = ea.y + ea.w;
            float cnt1 = eb.x + eb.z, ts1 = eb.y + eb.w;
            float tn0, tn1;

            if (u >= WV / 4) {               // both voxels jj >= 60
                float4 xa = Cq[((ro - 120) >> 1) + 0];
                float4 xb = Cq[((ro - 120) >> 1) + 1];
                cnt0 += xa.x + xa.z;  ts0 += xa.y + xa.w;
                cnt1 += xb.x + xb.z;  ts1 += xb.y + xb.w;
                tn0 = ts0 / Tk;  tn1 = ts1 / Tk;
            } else if (ii >= 1) {            // both jj < 60, interior row
                float4 xa = Cq[((re - 120) >> 1) + 0];
                float4 xb = Cq[((re - 120) >> 1) + 1];
                cnt0 += xa.x + xa.z;  ts0 += xa.y + xa.w;
                cnt1 += xb.x + xb.z;  ts1 += xb.y + xb.w;
                tn0 = ts0 / Tk;  tn1 = ts1 / Tk;
            } else {                         // ii == 0, jj < 60: inflow from k-1 row 179
                tn0 = ts0 / Tk;  tn1 = ts1 / Tk;
                if (k > 0) {
                    int sp = (k - 1) * (HH * WW) + (HH - 1) * WW + 120 + 4 * u;
                    float4 xa = Cq[(sp >> 1) + 0];
                    float4 xb = Cq[(sp >> 1) + 1];
                    float Tp = __uint_as_float(g_small[2 + k - 1]);
                    if (Tp == 0.0f) Tp = 1.0f;
                    cnt0 += xa.x + xa.z;  tn0 += (xa.y + xa.w) / Tp;
                    cnt1 += xb.x + xb.z;  tn1 += (xb.y + xb.w) / Tp;
                }
            }

            reinterpret_cast<float2*>(counter + v0)[0] = make_float2(cnt0, cnt1);
            reinterpret_cast<float2*>(timer + v0)[0] = make_float2(
                tn0 / (cnt0 == 0.0f ? 1.0f : cnt0),
                tn1 / (cnt1 == 0.0f ? 1.0f : cnt1));
        }
    }
}

// ---------------------------------------------------------------------------
extern "C" void kernel_launch(void* const* d_in, const int* in_sizes, int n_in,
                              void* d_out, int out_size)
{
    const float* ev = (const float*)d_in[0];
    int n = in_sizes[0] / 5;
    float* out = (float*)d_out;

    // guaranteed-resident grid (recomputed every call — deterministic, no caching)
    int dev = 0;            cudaGetDevice(&dev);
    int smCount = 0;        cudaDeviceGetAttribute(&smCount, cudaDevAttrMultiProcessorCount, dev);
    int bpsm = 0;
    cudaOccupancyMaxActiveBlocksPerMultiprocessor(&bpsm, fused_kernel, 256, 0);
    if (bpsm < 1) bpsm = 1;
    int grid = smCount * bpsm;

    // zero barrier counters + tmax slots each launch (128 B)
    void* p_sm = nullptr;   cudaGetSymbolAddress(&p_sm, g_small);
    cudaMemsetAsync(p_sm, 0, sizeof(unsigned) * 32);

    int nTiles = (n + TILE_EV - 1) / TILE_EV;
    fused_kernel<<<grid, 256>>>((const float4*)ev, n, nTiles, out);
}

// round 11
// speedup vs baseline: 1.1664x; 1.1664x over previous
#include <cuda_runtime.h>
#include <cuda_bf16.h>
#include <cstdint>

#define BB 16
#define HH 180
#define WW 240
#define NC (BB*HH*WW)      /* 691200 full-res cells            */
#define HV (HH/2)          /* 90                               */
#define WV (WW/2)          /* 120                              */
#define VPB (HV*WV)        /* 10800 voxels per batch           */
#define NV (BB*VPB)        /* 172800 half-res voxels           */

#define TILE_EV    1024
#define TILE_BYTES (TILE_EV * 20)   /* 20480 B per tile */

// Scratch (__device__ globals — no allocations allowed)
__device__ float2   g_ct[NC];      // per full-res cell: (count, tsum_raw)
__device__ unsigned g_tmax[BB];    // per-batch max(t) as uint bits (t >= 0)

// ---------------------------------------------------------------------------
__device__ __forceinline__ uint32_t smem_u32(const void* p) {
    uint32_t a;
    asm("{ .reg .u64 t; cvta.to.shared.u64 t, %1; cvt.u32.u64 %0, t; }"
        : "=r"(a) : "l"(p));
    return a;
}

__device__ __forceinline__ void mbar_init(uint32_t mb, unsigned cnt) {
    asm volatile("mbarrier.init.shared.b64 [%0], %1;" :: "r"(mb), "r"(cnt) : "memory");
}
__device__ __forceinline__ void mbar_expect_tx(uint32_t mb, unsigned bytes) {
    asm volatile("mbarrier.arrive.expect_tx.shared.b64 _, [%0], %1;"
                 :: "r"(mb), "r"(bytes) : "memory");
}
__device__ __forceinline__ void bulk_g2s(uint32_t dst, const void* src,
                                         unsigned bytes, uint32_t mb) {
    asm volatile("cp.async.bulk.shared::cluster.global.mbarrier::complete_tx::bytes "
                 "[%0], [%1], %2, [%3];"
                 :: "r"(dst), "l"(src), "r"(bytes), "r"(mb) : "memory");
}
__device__ __forceinline__ void mbar_wait(uint32_t mb, unsigned phase) {
    asm volatile(
        "{\n\t"
        ".reg .pred P1;\n\t"
        "WAIT_%=:\n\t"
        "mbarrier.try_wait.parity.acquire.cta.shared::cta.b64 P1, [%0], %1, 0x989680;\n\t"
        "@P1 bra DONE_%=;\n\t"
        "bra WAIT_%=;\n\t"
        "DONE_%=:\n\t"
        "}"
        :: "r"(mb), "r"(phase) : "memory");
}

// ---------------------------------------------------------------------------
__global__ void init_kernel() {
    int i = blockIdx.x * blockDim.x + threadIdx.x;
    int stride = gridDim.x * blockDim.x;
    float4* p = reinterpret_cast<float4*>(g_ct);   // NC float2 = NC/2 float4
    for (int j = i; j < NC / 2; j += stride)
        p[j] = make_float4(0.f, 0.f, 0.f, 0.f);
    if (i < BB) g_tmax[i] = 0u;
}

// ---------------------------------------------------------------------------
// Scatter with TMA-staged (cp.async.bulk) double-buffered event tiles:
// event loads bypass L1tex entirely, leaving the pipe for the REDs.
__global__ void __launch_bounds__(256) scatter_kernel(
    const float* __restrict__ ev, int n, int nTiles)
{
    __shared__ __align__(128) float sbuf[2][TILE_EV * 5];   // 2 x 20 KB
    __shared__ __align__(8) unsigned long long mbar[2];
    __shared__ unsigned smax[BB];

    const unsigned FULL = 0xffffffffu;
    const int NB = gridDim.x;
    int lane = threadIdx.x & 31;
    unsigned loc = 0;  // lane l (<16) carries running max-bits for batch l

    long long totBytes = (long long)n * 20;
    const char* evb = reinterpret_cast<const char*>(ev);

    int myTiles = (blockIdx.x < nTiles) ? (nTiles - blockIdx.x + NB - 1) / NB : 0;

    uint32_t mb[2]  = { smem_u32(&mbar[0]), smem_u32(&mbar[1]) };
    uint32_t sba[2] = { smem_u32(&sbuf[0][0]), smem_u32(&sbuf[1][0]) };

    if (threadIdx.x == 0) {
        mbar_init(mb[0], 1);
        mbar_init(mb[1], 1);
    }
    if (threadIdx.x < BB) smax[threadIdx.x] = 0u;
    __syncthreads();

    // prologue: issue copies for j = 0, 1
    if (threadIdx.x == 0) {
        #pragma unroll
        for (int j = 0; j < 2; ++j) {
            if (j < myTiles) {
                long long base = ((long long)blockIdx.x + (long long)j * NB) * TILE_BYTES;
                unsigned sz  = (unsigned)min((long long)TILE_BYTES, totBytes - base);
                unsigned m16 = sz & ~15u;
                mbar_expect_tx(mb[j], m16);
                bulk_g2s(sba[j], evb + base, m16, mb[j]);
            }
        }
    }

    for (int j = 0; j < myTiles; ++j) {
        int s = j & 1;
        mbar_wait(mb[s], (unsigned)((j >> 1) & 1));

        int tile = blockIdx.x + j * NB;
        long long baseEv = (long long)tile * TILE_EV;
        long long base   = baseEv * 20;
        unsigned  sz     = (unsigned)min((long long)TILE_BYTES, totBytes - base);
        int evFull = (int)((sz & ~15u) / 20);   // events fully covered by the copy
        const float* sf = sbuf[s];

        #pragma unroll
        for (int q = 0; q < 4; ++q) {
            int le = threadIdx.x + q * 256;
            long long e = baseEv + le;
            bool valid = (e < (long long)n);
            float x = 0.f, y = 0.f, t = 0.f, b = 0.f;
            if (valid) {
                if (le < evFull) {                  // staged path (smem)
                    int sidx = 5 * le;
                    x = sf[sidx + 0];
                    y = sf[sidx + 1];
                    t = sf[sidx + 2];
                    b = sf[sidx + 4];
                } else {                            // rare 16B-alignment tail
                    const float* p = ev + e * 5;
                    x = __ldg(p + 0); y = __ldg(p + 1);
                    t = __ldg(p + 2); b = __ldg(p + 4);
                }
            }
            int bi = (int)b, xi = (int)x, yi = (int)y;

            if (valid) {
                // single fused atomic per event: (count, raw t) into full-res cell
                int idx_c = xi + WW * yi + (WW * HH) * bi;
                if ((unsigned)idx_c < (unsigned)NC)
                    asm volatile("red.global.add.v2.f32 [%0], {%1, %2};"
                                 :: "l"(&g_ct[idx_c]), "f"(1.0f), "f"(t) : "memory");
            }

            // per-batch time max: b sorted -> warps almost always batch-uniform
            unsigned tb = __float_as_uint(t);
            int b0 = __shfl_sync(FULL, bi, 0);
            if (__all_sync(FULL, bi == b0)) {
                unsigned wm = __reduce_max_sync(FULL, tb);
                if (lane == b0) loc = max(loc, wm);
            } else {
                for (int l = 0; l < 32; ++l) {
                    int      bl = __shfl_sync(FULL, bi, l);
                    unsigned tl = __shfl_sync(FULL, tb, l);
                    if (lane == bl) loc = max(loc, tl);
                }
            }
        }
        __syncthreads();   // everyone done reading buf[s]

        int nj = j + 2;    // refill this buffer
        if (nj < myTiles && threadIdx.x == 0) {
            long long nbase = ((long long)blockIdx.x + (long long)nj * NB) * TILE_BYTES;
            unsigned nsz  = (unsigned)min((long long)TILE_BYTES, totBytes - nbase);
            unsigned m16  = nsz & ~15u;
            mbar_expect_tx(mb[s], m16);
            bulk_g2s(sba[s], evb + nbase, m16, mb[s]);
        }
    }

    // tmax epilogue
    if (lane < BB && loc) atomicMax(&smax[lane], loc);
    __syncthreads();
    if (threadIdx.x < BB && smax[threadIdx.x])
        atomicMax(&g_tmax[threadIdx.x], smax[threadIdx.x]);
}

// ---------------------------------------------------------------------------
// One thread per half-res voxel (R5-proven shape). Voxel (k, ii, jj)
// aggregates, per the reference's idx_k = floor(x/2) + 60*y + 10800*b quirk:
//   even row y=2ii, cols [2jj, 2jj+1]                       (always)
//   jj >= 60: odd row y=2ii+1, cols [2jj-120, 2jj-119]      (same batch)
//   jj <  60, ii >= 1: odd row y=2ii-1, cols [120+2jj, 121+2jj]
//   jj <  60, ii == 0, k >= 1: batch k-1, row 179, cols [120+2jj, 121+2jj]
__global__ void finalize_kernel(float* __restrict__ out) {
    int v = blockIdx.x * blockDim.x + threadIdx.x;
    if (v >= NV) return;

    float* cont    = out;
    float* counter = out + NC;
    float* timer   = out + NC + NV;
    float* dxo     = out + NC + 2 * NV;
    float* dyo     = out + NC + 3 * NV;

    int k  = v / VPB;
    int rr = v - k * VPB;
    int ii = rr / WV;
    int jj = rr - ii * WV;

    const float2* Cb = g_ct + k * (HH * WW);
    int re = (2 * ii) * WW + 2 * jj;    // even row (2ii) base
    int ro = re + WW;                   // odd row (2ii+1) base
    float2 c00 = Cb[re], c01 = Cb[re + 1];
    float2 c10 = Cb[ro], c11 = Cb[ro + 1];

    // container output (full-res counts) — 2x2 block tiles the grid exactly
    int cb = k * (HH * WW);
    cont[cb + re]     = c00.x;
    cont[cb + re + 1] = c01.x;
    cont[cb + ro]     = c10.x;
    cont[cb + ro + 1] = c11.x;

    // strided diffs on the full-res histogram
    dxo[v] = (c10.x - c11.x) + (c00.x - c01.x);
    dyo[v] = (c00.x - c10.x) + (c01.x - c11.x);

    float Tk = __uint_as_float(g_tmax[k]);
    if (Tk == 0.0f) Tk = 1.0f;

    float cnt = c00.x + c01.x;
    float ts  = c00.y + c01.y;
    float tn;

    if (jj >= WV / 2) {
        float2 o0 = Cb[ro - 120], o1 = Cb[ro - 119];
        cnt += o0.x + o1.x;  ts += o0.y + o1.y;
        tn = ts / Tk;
    } else if (ii >= 1) {
        float2 o0 = Cb[re - 120], o1 = Cb[re - 119];
        cnt += o0.x + o1.x;  ts += o0.y + o1.y;
        tn = ts / Tk;
    } else {
        tn = ts / Tk;
        if (k > 0) {
            const float2* Cp = g_ct + (k - 1) * (HH * WW) + (HH - 1) * WW;
            float2 s0 = Cp[120 + 2 * jj];
            float2 s1 = Cp[121 + 2 * jj];
            float Tp = __uint_as_float(g_tmax[k - 1]);
            if (Tp == 0.0f) Tp = 1.0f;
            cnt += s0.x + s1.x;
            tn  += (s0.y + s1.y) / Tp;
        }
    }

    counter[v] = cnt;
    timer[v]   = tn / (cnt == 0.0f ? 1.0f : cnt);
}

// ---------------------------------------------------------------------------
extern "C" void kernel_launch(void* const* d_in, const int* in_sizes, int n_in,
                              void* d_out, int out_size)
{
    const float* ev = (const float*)d_in[0];
    int n = in_sizes[0] / 5;
    float* out = (float*)d_out;

    int nTiles = (n + TILE_EV - 1) / TILE_EV;
    init_kernel<<<1024, 256>>>();
    scatter_kernel<<<760, 256>>>(ev, n, nTiles);   // 5 blocks/SM (41 KB smem each)
    finalize_kernel<<<(NV + 255) / 256, 256>>>(out);
}